// round 15
// baseline (speedup 1.0000x reference)
#include <cuda_runtime.h>
#include <cuda_bf16.h>
#include <math.h>
#include <stdint.h>

// Problem constants
#define BB 64
#define TT 512
#define DD 1024
#define HH 1024
#define NGATE 4096            // 4*H
#define MM (BB*TT)            // 32768

// Persistent recurrence config
#define NCTA 128
#define NTHR 256

// GEMM smem (bf16 elems)
#define GAP (128*40)
#define GBP (64*40)
#define GEMM_SMEM_BYTES ((4*GAP + 4*GBP)*2)              // 61440

// LSTM smem layout (bytes)
#define PW_BYTES (64*32*4*16)        // packed W: 131072 (hi+lo kept)
#define HTP 72                       // h_T row pitch in bf16 (64 + 8 pad)
#define CHUNK_BYTES (128*HTP*2)      // one K=128 chunk, hi plane only: 18432
#define NSTAGE 4
#define GP 34                        // gate-reduce pitch (floats)
#define GRED_BYTES (2*64*GP*4)       // 17408
#define SM_STAGES_OFF PW_BYTES
#define SM_GRED_OFF (PW_BYTES + NSTAGE*CHUNK_BYTES)      // 204800
#define SM_MBAR_OFF (SM_GRED_OFF + GRED_BYTES)           // 222208
#define LSTM_SMEM_BYTES (SM_MBAR_OFF + NSTAGE*8)         // 222240

// Scratch (device globals; no allocation allowed).
// NOTE: device globals are NEVER passed as kernel args from host (host shadow
// symbol trap, proven R10). All device-global selection happens device-side.
// Gx / y0 planes are time-major: row m = t*BB + b.
// h state lives TRANSPOSED [unit][batch], hi plane ONLY (bf16x2 recurrence:
// products hi_h*hi_W + hi_h*lo_W; the dropped lo_h*W term is ~2^-9 of the
// recurrence contribution -> final rel_err ~1e-4, threshold 1e-3).
__device__ float g_Gx[(size_t)MM * NGATE];        // [T,B,4H] projections+biases
__device__ __nv_bfloat16 g_Ahi[(size_t)MM * DD];  // GEMM A planes (x, then y0)
__device__ __nv_bfloat16 g_Alo[(size_t)MM * DD];
__device__ __nv_bfloat16 g_Whi[(size_t)2 * NGATE * DD];  // W_ih planes
__device__ __nv_bfloat16 g_Wlo[(size_t)2 * NGATE * DD];
__device__ __align__(256) __nv_bfloat16 g_hThi[2][HH * HTP];  // [parity][unit][b]
__device__ float g_h[2][2][BB * HH];              // fp32 h (init + tail only)
__device__ float g_c[2][BB * HH];                 // fp32 c (init + tail only)
__device__ unsigned g_bar[2];

// bf16x3 split: x ~= hi + lo, packed 2 consecutive-k elements per u32
__device__ __forceinline__ void split2(float x, float y, unsigned& hi, unsigned& lo) {
    __nv_bfloat16 hx = __float2bfloat16(x);
    __nv_bfloat16 hy = __float2bfloat16(y);
    __nv_bfloat16 lx = __float2bfloat16(x - __bfloat162float(hx));
    __nv_bfloat16 ly = __float2bfloat16(y - __bfloat162float(hy));
    hi = (unsigned)__bfloat16_as_ushort(hx) | ((unsigned)__bfloat16_as_ushort(hy) << 16);
    lo = (unsigned)__bfloat16_as_ushort(lx) | ((unsigned)__bfloat16_as_ushort(ly) << 16);
}

__device__ __forceinline__ void mma_bf16(float c[4], const unsigned a[4], const unsigned b[2]) {
    asm volatile(
        "mma.sync.aligned.m16n8k16.row.col.f32.bf16.bf16.f32 "
        "{%0,%1,%2,%3}, {%4,%5,%6,%7}, {%8,%9}, {%0,%1,%2,%3};\n"
        : "+f"(c[0]), "+f"(c[1]), "+f"(c[2]), "+f"(c[3])
        : "r"(a[0]), "r"(a[1]), "r"(a[2]), "r"(a[3]), "r"(b[0]), "r"(b[1]));
}

// ldmatrix x4 transposed: A fragment from k-major [k][m] tiles
__device__ __forceinline__ void ldsm_x4t(unsigned r[4], unsigned saddr) {
    asm volatile("ldmatrix.sync.aligned.m8n8.x4.trans.shared.b16 {%0,%1,%2,%3}, [%4];"
                 : "=r"(r[0]), "=r"(r[1]), "=r"(r[2]), "=r"(r[3]) : "r"(saddr));
}

__device__ __forceinline__ void cpa16(void* dst, const void* src) {
    unsigned d = (unsigned)__cvta_generic_to_shared(dst);
    asm volatile("cp.async.cg.shared.global [%0], [%1], 16;\n" :: "r"(d), "l"(src));
}
__device__ __forceinline__ void cpa_commit() { asm volatile("cp.async.commit_group;\n"); }
__device__ __forceinline__ void cpa_wait1()  { asm volatile("cp.async.wait_group 1;\n"); }
__device__ __forceinline__ void cpa_wait0()  { asm volatile("cp.async.wait_group 0;\n"); }

__device__ __forceinline__ void bulk_g2s(unsigned dst, const void* src, unsigned bytes,
                                         unsigned mbar) {
    asm volatile(
        "cp.async.bulk.shared::cluster.global.mbarrier::complete_tx::bytes [%0], [%1], %2, [%3];"
        :: "r"(dst), "l"(src), "r"(bytes), "r"(mbar) : "memory");
}
__device__ __forceinline__ void mbar_init(unsigned mb, unsigned cnt) {
    asm volatile("mbarrier.init.shared.b64 [%0], %1;" :: "r"(mb), "r"(cnt) : "memory");
}
__device__ __forceinline__ void mbar_expect_tx(unsigned mb, unsigned bytes) {
    asm volatile("mbarrier.arrive.expect_tx.shared.b64 _, [%0], %1;"
                 :: "r"(mb), "r"(bytes) : "memory");
}
__device__ __forceinline__ void mbar_wait(unsigned mb, unsigned ph) {
    asm volatile(
        "{\n\t"
        ".reg .pred P1;\n\t"
        "WL_%=:\n\t"
        "mbarrier.try_wait.parity.acquire.cta.shared::cta.b64 P1, [%0], %1, 0x989680;\n\t"
        "@P1 bra.uni WD_%=;\n\t"
        "bra.uni WL_%=;\n\t"
        "WD_%=:\n\t"
        "}"
        :: "r"(mb), "r"(ph) : "memory");
}
__device__ __forceinline__ void fence_proxy_async_() {
    asm volatile("fence.proxy.async;" ::: "memory");
}

__device__ __forceinline__ float sigmoidf_(float x) { return 1.0f / (1.0f + expf(-x)); }

// ---------------------------------------------------------------------------
// init: hx, cx -> state buffers (parity 0); reset barrier counters
// ---------------------------------------------------------------------------
__global__ void init_kernel(const float* __restrict__ hx, const float* __restrict__ cx) {
    int i = blockIdx.x * blockDim.x + threadIdx.x;   // over B*L*H = 131072
    if (i == 0) { g_bar[0] = 0u; g_bar[1] = 0u; }
    if (i >= BB * 2 * HH) return;
    int b = i >> 11;
    int l = (i >> 10) & 1;
    int k = i & 1023;
    g_h[l][0][b * HH + k] = hx[i];
    g_c[l][b * HH + k] = cx[i];
}

// ---------------------------------------------------------------------------
// prep: fp32 -> bf16 hi/lo planes; x [B,T,D] -> time-major rows m = t*BB+b
// ---------------------------------------------------------------------------
__global__ void prep_x_kernel(const float* __restrict__ x) {
    size_t i = (size_t)blockIdx.x * 256 + threadIdx.x;   // < MM*DD/4
    float4 v = reinterpret_cast<const float4*>(x)[i];
    unsigned h0, l0, h1, l1;
    split2(v.x, v.y, h0, l0);
    split2(v.z, v.w, h1, l1);
    size_t row_in = i >> 8;            // b*TT + t
    size_t d4 = i & 255;
    size_t b = row_in >> 9, t = row_in & 511;
    size_t o = (t * BB + b) * 256 + d4;
    reinterpret_cast<uint2*>(g_Ahi)[o] = make_uint2(h0, h1);
    reinterpret_cast<uint2*>(g_Alo)[o] = make_uint2(l0, l1);
}

__global__ void prep_w_kernel(const float* __restrict__ Wih) {
    size_t i = (size_t)blockIdx.x * 256 + threadIdx.x;
    float4 v = reinterpret_cast<const float4*>(Wih)[i];
    unsigned h0, l0, h1, l1;
    split2(v.x, v.y, h0, l0);
    split2(v.z, v.w, h1, l1);
    reinterpret_cast<uint2*>(g_Whi)[i] = make_uint2(h0, h1);
    reinterpret_cast<uint2*>(g_Wlo)[i] = make_uint2(l0, l1);
}

// h0 fp32 -> transposed hi plane (parity 0), per layer
__global__ void hplane_init_kernel(int layer) {
    int i = blockIdx.x * blockDim.x + threadIdx.x;   // over H*B = 65536
    if (i >= HH * BB) return;
    int j = i >> 6, b = i & 63;
    float v = g_h[layer][0][b * HH + j];
    g_hThi[0][j * HTP + b] = __float2bfloat16(v);
}

// ---------------------------------------------------------------------------
// Big GEMM (bf16x3, cp.async double-buffered) — unchanged (proven R11-R13).
// g_Gx[m,4096] = A_planes[m,1024] * W_planes[4096,1024]^T + b_ih + b_hh
// ---------------------------------------------------------------------------
__global__ void __launch_bounds__(256) gemm_bias_v2(
    int layer, const float* __restrict__ bia, const float* __restrict__ bib) {
    extern __shared__ unsigned char smem_raw[];
    __nv_bfloat16* sm16 = (__nv_bfloat16*)smem_raw;
    __nv_bfloat16* sA_hi = sm16;                 // [2][GAP]
    __nv_bfloat16* sA_lo = sm16 + 2 * GAP;
    __nv_bfloat16* sB_hi = sm16 + 4 * GAP;       // [2][GBP]
    __nv_bfloat16* sB_lo = sm16 + 4 * GAP + 2 * GBP;

    const __nv_bfloat16* __restrict__ Whi = g_Whi + (size_t)layer * NGATE * DD;
    const __nv_bfloat16* __restrict__ Wlo = g_Wlo + (size_t)layer * NGATE * DD;

    const int tid = threadIdx.x;
    const int wid = tid >> 5, lane = tid & 31;
    const int g = lane >> 2, t4 = lane & 3;
    const int wm = wid & 3, wn = wid >> 2;
    const int m0 = blockIdx.y * 128, n0 = blockIdx.x * 64;

    float acc[2][4][4];
#pragma unroll
    for (int s = 0; s < 2; s++)
#pragma unroll
        for (int n = 0; n < 4; n++)
#pragma unroll
            for (int i = 0; i < 4; i++) acc[s][n][i] = 0.0f;

    auto issue = [&](int c) {
        int st = c & 1, k0 = c * 32;
#pragma unroll
        for (int i = 0; i < 2; i++) {
            int e = tid + i * 256;
            int r = e >> 2, sg = e & 3;
            size_t so = (size_t)(m0 + r) * DD + k0 + sg * 8;
            int dof = st * GAP + r * 40 + sg * 8;
            cpa16(sA_hi + dof, g_Ahi + so);
            cpa16(sA_lo + dof, g_Alo + so);
        }
        {
            int r = tid >> 2, sg = tid & 3;
            size_t so = (size_t)(n0 + r) * DD + k0 + sg * 8;
            int dof = st * GBP + r * 40 + sg * 8;
            cpa16(sB_hi + dof, Whi + so);
            cpa16(sB_lo + dof, Wlo + so);
        }
        cpa_commit();
    };

    issue(0);
    for (int c = 0; c < 32; c++) {
        if (c < 31) { issue(c + 1); cpa_wait1(); } else { cpa_wait0(); }
        __syncthreads();
        const __nv_bfloat16* Ah = sA_hi + (c & 1) * GAP;
        const __nv_bfloat16* Al = sA_lo + (c & 1) * GAP;
        const __nv_bfloat16* Bh = sB_hi + (c & 1) * GBP;
        const __nv_bfloat16* Bl = sB_lo + (c & 1) * GBP;
#pragma unroll
        for (int kc = 0; kc < 32; kc += 16) {
            unsigned ahi[2][4], alo[2][4];
#pragma unroll
            for (int s = 0; s < 2; s++) {
                int r0 = (wm * 32 + s * 16 + g) * 40, r1 = r0 + 8 * 40;
                ahi[s][0] = *reinterpret_cast<const unsigned*>(&Ah[r0 + kc + 2 * t4]);
                ahi[s][1] = *reinterpret_cast<const unsigned*>(&Ah[r1 + kc + 2 * t4]);
                ahi[s][2] = *reinterpret_cast<const unsigned*>(&Ah[r0 + kc + 2 * t4 + 8]);
                ahi[s][3] = *reinterpret_cast<const unsigned*>(&Ah[r1 + kc + 2 * t4 + 8]);
                alo[s][0] = *reinterpret_cast<const unsigned*>(&Al[r0 + kc + 2 * t4]);
                alo[s][1] = *reinterpret_cast<const unsigned*>(&Al[r1 + kc + 2 * t4]);
                alo[s][2] = *reinterpret_cast<const unsigned*>(&Al[r0 + kc + 2 * t4 + 8]);
                alo[s][3] = *reinterpret_cast<const unsigned*>(&Al[r1 + kc + 2 * t4 + 8]);
            }
#pragma unroll
            for (int n = 0; n < 4; n++) {
                int nb = (wn * 32 + n * 8 + g) * 40;
                unsigned bhi[2], blo[2];
                bhi[0] = *reinterpret_cast<const unsigned*>(&Bh[nb + kc + 2 * t4]);
                bhi[1] = *reinterpret_cast<const unsigned*>(&Bh[nb + kc + 2 * t4 + 8]);
                blo[0] = *reinterpret_cast<const unsigned*>(&Bl[nb + kc + 2 * t4]);
                blo[1] = *reinterpret_cast<const unsigned*>(&Bl[nb + kc + 2 * t4 + 8]);
#pragma unroll
                for (int s = 0; s < 2; s++) {
                    mma_bf16(acc[s][n], ahi[s], bhi);
                    mma_bf16(acc[s][n], ahi[s], blo);
                    mma_bf16(acc[s][n], alo[s], bhi);
                }
            }
        }
        __syncthreads();
    }

#pragma unroll
    for (int s = 0; s < 2; s++) {
#pragma unroll
        for (int n = 0; n < 4; n++) {
            int row = m0 + wm * 32 + s * 16 + g;
            int col = n0 + wn * 32 + n * 8 + 2 * t4;
            float b0 = bia[col] + bib[col];
            float b1 = bia[col + 1] + bib[col + 1];
            g_Gx[(size_t)row * NGATE + col]           = acc[s][n][0] + b0;
            g_Gx[(size_t)row * NGATE + col + 1]       = acc[s][n][1] + b1;
            g_Gx[(size_t)(row + 8) * NGATE + col]     = acc[s][n][2] + b0;
            g_Gx[(size_t)(row + 8) * NGATE + col + 1] = acc[s][n][3] + b1;
        }
    }
}

// ---------------------------------------------------------------------------
// Persistent per-layer recurrence v5 (bf16x2, 4-stage bulk pipeline).
// 128 CTAs x 256 threads (1 CTA/SM). CTA owns 8 hidden units = 32 gate rows.
// W slice SMEM-resident packed hi+lo (exact W). h state: hi plane only.
// Per step: 8 chunks of K=128, 4 SMEM stages, issue depth 3. A-fragments via
// ldmatrix.trans; products hi_h*hi_W + hi_h*lo_W. c in registers.
// Chunk loop fully unrolled -> mbarrier parities are compile-time constants
// (each stage completes exactly twice per step -> parity pattern 0,1 / step).
// ---------------------------------------------------------------------------
__global__ void __launch_bounds__(NTHR, 1) lstm_layer_v5(
    const float* __restrict__ Whh, int layer, float* __restrict__ dout, int baridx) {
    extern __shared__ unsigned char smem_raw[];
    unsigned* pW = (unsigned*)smem_raw;                       // packed W u32s
    float* Gred = (float*)(smem_raw + SM_GRED_OFF);           // [2][64][GP]
    const unsigned smem_base = (unsigned)__cvta_generic_to_shared(smem_raw);
    const unsigned stages_sm = smem_base + SM_STAGES_OFF;
    const unsigned mbar_sm   = smem_base + SM_MBAR_OFF;       // NSTAGE x 8B

    const int tid = threadIdx.x;
    const int wid = tid >> 5, lane = tid & 31;
    const int g = lane >> 2, t4 = lane & 3;
    const int mt = wid & 3;                 // batch m16 tile
    const int kh = wid >> 2;                // K half (0/1) within 128-k chunk
    const int j0 = blockIdx.x * 8;          // hidden-unit base

    if (tid == 0) {
#pragma unroll
        for (int s = 0; s < NSTAGE; s++) mbar_init(mbar_sm + s * 8, 1);
        fence_proxy_async_();
    }

    // ---- load W slice into packed per-lane fragment layout, once ----
#pragma unroll 4
    for (int i = 0; i < 32; i++) {
        int e = tid + i * NTHR;              // 8192 float4
        int r = e >> 8, kf = e & 255;
        int q = r >> 3, jl = r & 7;
        int k0 = kf * 4;
        float4 v = *reinterpret_cast<const float4*>(
            &Whh[(size_t)(q * HH + j0 + jl) * HH + k0]);
        unsigned h0, l0, h1, l1;
        split2(v.x, v.y, h0, l0);
        split2(v.z, v.w, h1, l1);
        int kb = k0 >> 4;
        {
            int tp = (k0 >> 1) & 3, sl = (k0 >> 3) & 1;
            int base = ((kb * 32 + r) * 4 + tp) * 4;
            pW[base + sl] = h0;
            pW[base + 2 + sl] = l0;
        }
        {
            int k2 = k0 + 2;
            int tp = (k2 >> 1) & 3, sl = (k2 >> 3) & 1;
            int base = ((kb * 32 + r) * 4 + tp) * 4;
            pW[base + sl] = h1;
            pW[base + 2 + sl] = l1;
        }
    }
    __syncthreads();

    // ---- c in registers; cell-update mapping: (b = tid&63, 2 units) ----
    const int cb = tid & 63;
    const int ug = tid >> 6;
    const int jl2 = 2 * ug;
    float creg[2];
#pragma unroll
    for (int i = 0; i < 2; i++)
        creg[i] = g_c[layer][cb * HH + j0 + jl2 + i];

    // ldmatrix.trans per-lane byte offset within a [128 k][HTP] tile
    const int lm_row = (lane & 7) + ((lane >> 4) << 3);
    const int lm_col = mt * 16 + ((lane >> 3) & 1) * 8;
    const unsigned lm_byte = (unsigned)(lm_row * HTP + lm_col) * 2u;

    unsigned bar_target = 0;

    for (int t = 0; t < TT; t++) {
        const int par = t & 1, parn = par ^ 1;
        const __nv_bfloat16* __restrict__ hTh = g_hThi[par];

        // ---- issue chunks 0..2 (depth-3 into 4 stages) ----
        if (tid == 0) {
            fence_proxy_async_();
#pragma unroll
            for (int c = 0; c < 3; c++) {
                unsigned mb = mbar_sm + c * 8;
                mbar_expect_tx(mb, CHUNK_BYTES);
                bulk_g2s(stages_sm + c * CHUNK_BYTES,
                         hTh + (size_t)c * 128 * HTP, CHUNK_BYTES, mb);
            }
        }

        // ---- prefetch Gx for this step ----
        float2 pgx[4];
        {
            size_t gbase = ((size_t)t * BB + cb) * NGATE + j0 + jl2;
#pragma unroll
            for (int q = 0; q < 4; q++)
                pgx[q] = __ldg(reinterpret_cast<const float2*>(&g_Gx[gbase + q * HH]));
        }

        float acc[4][4];
#pragma unroll
        for (int n = 0; n < 4; n++)
#pragma unroll
            for (int i = 0; i < 4; i++) acc[n][i] = 0.0f;

#pragma unroll
        for (int c = 0; c < 8; c++) {
            const int s = c & (NSTAGE - 1);
            const unsigned parity = (c >= NSTAGE) ? 1u : 0u;   // compile-time
            mbar_wait(mbar_sm + s * 8, parity);

            const unsigned hb_addr = stages_sm + s * CHUNK_BYTES + lm_byte;
#pragma unroll
            for (int kk = 0; kk < 4; kk++) {
                int kl = kh * 64 + kk * 16;
                unsigned ahi[4];
                ldsm_x4t(ahi, hb_addr + (unsigned)kl * (HTP * 2));
                int kb = c * 8 + kh * 4 + kk;
#pragma unroll
                for (int n = 0; n < 4; n++) {
                    const uint4 w = *reinterpret_cast<const uint4*>(
                        &pW[((kb * 32 + n * 8 + g) * 4 + t4) * 4]);
                    unsigned bhi[2] = {w.x, w.y};
                    unsigned blo[2] = {w.z, w.w};
                    mma_bf16(acc[n], ahi, bhi);
                    mma_bf16(acc[n], ahi, blo);
                }
            }
            __syncthreads();   // all warps done with stage s
            if (c < 5 && tid == 0) {
                int cn = c + 3;
                int sn = cn & (NSTAGE - 1);
                unsigned mb = mbar_sm + sn * 8;
                mbar_expect_tx(mb, CHUNK_BYTES);
                bulk_g2s(stages_sm + sn * CHUNK_BYTES,
                         hTh + (size_t)cn * 128 * HTP, CHUNK_BYTES, mb);
            }
        }

        // ---- split-K reduce via SMEM ----
#pragma unroll
        for (int n = 0; n < 4; n++) {
            int row = mt * 16 + g;
            int col = n * 8 + 2 * t4;
            float* gp = &Gred[(kh * 64 + row) * GP + col];
            gp[0] = acc[n][0];
            gp[1] = acc[n][1];
            gp[8 * GP] = acc[n][2];
            gp[8 * GP + 1] = acc[n][3];
        }
        __syncthreads();

        // ---- gate/cell update: thread = (batch cb, units jl2, jl2+1) ----
        {
            float2 gr0[4], gr1[4];
#pragma unroll
            for (int q = 0; q < 4; q++) {
                gr0[q] = *reinterpret_cast<const float2*>(&Gred[(cb) * GP + q * 8 + jl2]);
                gr1[q] = *reinterpret_cast<const float2*>(&Gred[(64 + cb) * GP + q * 8 + jl2]);
            }
#pragma unroll
            for (int i = 0; i < 2; i++) {
                float gi, gf, gg, go;
                if (i == 0) {
                    gi = pgx[0].x + gr0[0].x + gr1[0].x;
                    gf = pgx[1].x + gr0[1].x + gr1[1].x;
                    gg = pgx[2].x + gr0[2].x + gr1[2].x;
                    go = pgx[3].x + gr0[3].x + gr1[3].x;
                } else {
                    gi = pgx[0].y + gr0[0].y + gr1[0].y;
                    gf = pgx[1].y + gr0[1].y + gr1[1].y;
                    gg = pgx[2].y + gr0[2].y + gr1[2].y;
                    go = pgx[3].y + gr0[3].y + gr1[3].y;
                }
                float iv = sigmoidf_(gi);
                float fv = sigmoidf_(gf);
                float gv = tanhf(gg);
                float ov = sigmoidf_(go);
                float cn = fv * creg[i] + iv * gv;
                float hn = ov * tanhf(cn);
                creg[i] = cn;
                int j = j0 + jl2 + i;
                __nv_bfloat16 hb = __float2bfloat16(hn);
                g_hThi[parn][j * HTP + cb] = hb;      // coalesced across cb
                if (t == TT - 1) {                    // parn == 0 at t=511
                    g_h[layer][0][cb * HH + j] = hn;
                    g_c[layer][cb * HH + j] = cn;
                }
                if (dout) {
                    dout[(size_t)(cb * TT + t) * HH + j] = hn;        // [B,T,H]
                } else {
                    // layer-0 y feeds the (bf16x3) GEMM: keep hi+lo planes
                    __nv_bfloat16 lb = __float2bfloat16(hn - __bfloat162float(hb));
                    size_t yo = ((size_t)t * BB + cb) * DD + j;
                    g_Ahi[yo] = hb;
                    g_Alo[yo] = lb;
                }
            }
        }

        // ---- grid barrier (release/acquire) ----
        bar_target += NCTA;
        __syncthreads();
        if (tid == 0) {
            __threadfence();
            atomicAdd(&g_bar[baridx], 1u);
            while (*((volatile unsigned*)&g_bar[baridx]) < bar_target) __nanosleep(32);
            __threadfence();
        }
        __syncthreads();
    }
}

// ---------------------------------------------------------------------------
// tail: final (h, c) of last layer after output
// ---------------------------------------------------------------------------
__global__ void tail_kernel(float* __restrict__ out) {
    int i = blockIdx.x * blockDim.x + threadIdx.x;   // over B*H = 65536
    if (i >= BB * HH) return;
    out[(size_t)MM * HH + i]           = g_h[1][0][i];
    out[(size_t)MM * HH + BB * HH + i] = g_c[1][i];
}

// ---------------------------------------------------------------------------
// Input classification by element count, signature-order fallback.
// ---------------------------------------------------------------------------
extern "C" void kernel_launch(void* const* d_in, const int* in_sizes, int n_in,
                              void* d_out, int out_size) {
    int idx_in = 0, idxW0 = 3, idxW1 = 4, idxB0 = 5, idxB1 = 6, idxS0 = 1, idxS1 = 2;
    {
        int fin = -1, fW[2] = {-1, -1}, fB[2] = {-1, -1}, fS[2] = {-1, -1};
        int nW = 0, nB = 0, nS = 0;
        for (int i = 0; i < n_in; i++) {
            long s = in_sizes[i];
            if (s == (long)MM * DD)              fin = i;
            else if (s == (long)2 * NGATE * DD)  { if (nW < 2) fW[nW++] = i; }
            else if (s == (long)BB * 2 * HH)     { if (nS < 2) fS[nS++] = i; }
            else if (s == (long)2 * NGATE)       { if (nB < 2) fB[nB++] = i; }
        }
        if (fin >= 0 && nW == 2 && nB == 2 && nS == 2) {
            bool sig = fin < fW[0];
            idx_in = fin;
            idxW0 = sig ? fW[0] : fW[1];  idxW1 = sig ? fW[1] : fW[0];
            idxS0 = sig ? fS[0] : fS[1];  idxS1 = sig ? fS[1] : fS[0];
            idxB0 = fB[0];  idxB1 = fB[1];
        }
    }
    const float* input_ = (const float*)d_in[idx_in];
    const float* hx     = (const float*)d_in[idxS0];
    const float* cx     = (const float*)d_in[idxS1];
    const float* W_ih   = (const float*)d_in[idxW0];
    const float* W_hh   = (const float*)d_in[idxW1];
    const float* b_ih   = (const float*)d_in[idxB0];
    const float* b_hh   = (const float*)d_in[idxB1];
    float* out = (float*)d_out;

    cudaFuncSetAttribute(gemm_bias_v2,
                         cudaFuncAttributeMaxDynamicSharedMemorySize, GEMM_SMEM_BYTES);
    cudaFuncSetAttribute(lstm_layer_v5,
                         cudaFuncAttributeMaxDynamicSharedMemorySize, LSTM_SMEM_BYTES);

    init_kernel<<<512, 256>>>(hx, cx);
    prep_x_kernel<<<32768, 256>>>(input_);
    prep_w_kernel<<<8192, 256>>>(W_ih);

    // Layer 0: projection from x planes, recurrence -> y planes (g_Ahi/g_Alo)
    gemm_bias_v2<<<dim3(64, 256), 256, GEMM_SMEM_BYTES>>>(0, b_ih, b_hh);
    hplane_init_kernel<<<256, 256>>>(0);
    lstm_layer_v5<<<NCTA, NTHR, LSTM_SMEM_BYTES>>>(W_hh, 0, nullptr, 0);

    // Layer 1: projection from y planes, recurrence -> out
    gemm_bias_v2<<<dim3(64, 256), 256, GEMM_SMEM_BYTES>>>(1, b_ih + NGATE, b_hh + NGATE);
    hplane_init_kernel<<<256, 256>>>(1);
    lstm_layer_v5<<<NCTA, NTHR, LSTM_SMEM_BYTES>>>(W_hh + (size_t)NGATE * HH, 1, out, 1);

    // Guarded tail: only write (hT, cT) if the output buffer has room.
    if (out_size >= (int)((size_t)MM * HH + 2 * (size_t)BB * HH))
        tail_kernel<<<256, 256>>>(out);
}

// round 17
// speedup vs baseline: 1.4923x; 1.4923x over previous
#include <cuda_runtime.h>
#include <cuda_fp16.h>
#include <math.h>
#include <stdint.h>

#define BB 64
#define TT 512
#define DD 1024
#define HH 1024
#define NGATE 4096
#define MM (BB*TT)

#define NCTA 128
#define NTHR 256

// GEMM smem (half elems)
#define GAP (128*40)
#define GBP (64*40)
#define GEMM_SMEM_BYTES ((2*GAP + 2*GBP)*2)              // 30720

// LSTM smem (bytes)
#define PW_BYTES 65536               // packed W fp16: [kbp32][row32][t4]uint4
#define HTP 72                       // h_T row pitch in half (64 + 8 pad)
#define CHUNK_BYTES (128*HTP*2)      // 18432
#define NSTAGE 4
#define GP 34
#define GRED_BYTES (2*64*GP*4)       // 17408
#define SM_STAGES_OFF PW_BYTES
#define SM_GRED_OFF (PW_BYTES + NSTAGE*CHUNK_BYTES)      // 139264
#define SM_MBAR_OFF (SM_GRED_OFF + GRED_BYTES)           // 156672
#define LSTM_SMEM_BYTES (SM_MBAR_OFF + NSTAGE*8)

// Scratch (device globals). NEVER passed from host (shadow-symbol trap, R10).
// Gx / y0 time-major: row m = t*BB + b. h transposed [unit][batch], fp16.
__device__ float g_Gx[(size_t)MM * NGATE];
__device__ __half g_Ah[(size_t)MM * DD];          // A plane fp16 (x, then y0)
__device__ __half g_Wih[(size_t)2 * NGATE * DD];  // W_ih fp16
__device__ __align__(256) __half g_hT[2][HH * HTP];
__device__ float g_h[2][2][BB * HH];
__device__ float g_c[2][BB * HH];
__device__ unsigned g_bar[2];

__device__ __forceinline__ unsigned pack2h(float x, float y) {
    __half2 h = __floats2half2_rn(x, y);
    return *reinterpret_cast<unsigned*>(&h);
}
__device__ __forceinline__ void mma_f16(float c[4], const unsigned a[4], const unsigned b[2]) {
    asm volatile("mma.sync.aligned.m16n8k16.row.col.f32.f16.f16.f32 "
        "{%0,%1,%2,%3}, {%4,%5,%6,%7}, {%8,%9}, {%0,%1,%2,%3};\n"
        : "+f"(c[0]), "+f"(c[1]), "+f"(c[2]), "+f"(c[3])
        : "r"(a[0]), "r"(a[1]), "r"(a[2]), "r"(a[3]), "r"(b[0]), "r"(b[1]));
}
__device__ __forceinline__ void ldsm_x4t(unsigned r[4], unsigned saddr) {
    asm volatile("ldmatrix.sync.aligned.m8n8.x4.trans.shared.b16 {%0,%1,%2,%3}, [%4];"
                 : "=r"(r[0]), "=r"(r[1]), "=r"(r[2]), "=r"(r[3]) : "r"(saddr));
}
__device__ __forceinline__ void cpa16(void* dst, const void* src) {
    unsigned d = (unsigned)__cvta_generic_to_shared(dst);
    asm volatile("cp.async.cg.shared.global [%0], [%1], 16;\n" :: "r"(d), "l"(src));
}
__device__ __forceinline__ void cpa_commit() { asm volatile("cp.async.commit_group;\n"); }
__device__ __forceinline__ void cpa_wait1()  { asm volatile("cp.async.wait_group 1;\n"); }
__device__ __forceinline__ void cpa_wait0()  { asm volatile("cp.async.wait_group 0;\n"); }
__device__ __forceinline__ void bulk_g2s(unsigned dst, const void* src, unsigned n, unsigned mb) {
    asm volatile("cp.async.bulk.shared::cluster.global.mbarrier::complete_tx::bytes [%0], [%1], %2, [%3];"
                 :: "r"(dst), "l"(src), "r"(n), "r"(mb) : "memory");
}
__device__ __forceinline__ void mbar_init(unsigned mb, unsigned c) {
    asm volatile("mbarrier.init.shared.b64 [%0], %1;" :: "r"(mb), "r"(c) : "memory");
}
__device__ __forceinline__ void mbar_tx(unsigned mb, unsigned n) {
    asm volatile("mbarrier.arrive.expect_tx.shared.b64 _, [%0], %1;" :: "r"(mb), "r"(n) : "memory");
}
__device__ __forceinline__ void mbar_wait(unsigned mb, unsigned ph) {
    asm volatile("{\n\t.reg .pred P1;\n\tWL_%=:\n\t"
        "mbarrier.try_wait.parity.acquire.cta.shared::cta.b64 P1, [%0], %1, 0x989680;\n\t"
        "@P1 bra.uni WD_%=;\n\tbra.uni WL_%=;\n\tWD_%=:\n\t}"
        :: "r"(mb), "r"(ph) : "memory");
}
__device__ __forceinline__ void fpa() { asm volatile("fence.proxy.async;" ::: "memory"); }
__device__ __forceinline__ float sigmoidf_(float x) { return 1.0f / (1.0f + expf(-x)); }

__global__ void init_kernel(const float* __restrict__ hx, const float* __restrict__ cx) {
    int i = blockIdx.x * blockDim.x + threadIdx.x;
    if (i == 0) { g_bar[0] = 0u; g_bar[1] = 0u; }
    if (i >= BB * 2 * HH) return;
    int b = i >> 11, l = (i >> 10) & 1, k = i & 1023;
    g_h[l][0][b * HH + k] = hx[i];
    g_c[l][b * HH + k] = cx[i];
}

// x [B,T,D] fp32 -> g_Ah fp16, time-major rows m = t*BB + b
__global__ void prep_x_kernel(const float* __restrict__ x) {
    size_t i = (size_t)blockIdx.x * 256 + threadIdx.x;   // < MM*DD/4
    float4 v = reinterpret_cast<const float4*>(x)[i];
    size_t row = i >> 8, d4 = i & 255;
    size_t b = row >> 9, t = row & 511;
    size_t o = (t * BB + b) * 256 + d4;
    reinterpret_cast<uint2*>(g_Ah)[o] = make_uint2(pack2h(v.x, v.y), pack2h(v.z, v.w));
}

__global__ void prep_w_kernel(const float* __restrict__ Wih) {
    size_t i = (size_t)blockIdx.x * 256 + threadIdx.x;   // < 2*NGATE*DD/4
    float4 v = reinterpret_cast<const float4*>(Wih)[i];
    reinterpret_cast<uint2*>(g_Wih)[i] = make_uint2(pack2h(v.x, v.y), pack2h(v.z, v.w));
}

__global__ void hplane_init_kernel(int layer) {
    int i = blockIdx.x * blockDim.x + threadIdx.x;   // H*B
    if (i >= HH * BB) return;
    int j = i >> 6, b = i & 63;
    g_hT[0][j * HTP + b] = __float2half_rn(g_h[layer][0][b * HH + j]);
}

// ---------------- GEMM fp16 x1 (R14 structure, planes halved) ----------------
// g_Gx[m,4096] = A[m,1024] * W[4096,1024]^T + b_ih + b_hh
__global__ void __launch_bounds__(256) gemm_bias_v3(
    int layer, const float* __restrict__ bia, const float* __restrict__ bib) {
    extern __shared__ unsigned char smem_raw[];
    __half* sA = (__half*)smem_raw;              // [2][GAP]
    __half* sB = sA + 2 * GAP;                   // [2][GBP]
    const __half* __restrict__ W = g_Wih + (size_t)layer * NGATE * DD;

    const int tid = threadIdx.x;
    const int wid = tid >> 5, lane = tid & 31;
    const int g = lane >> 2, t4 = lane & 3;
    const int wm = wid & 3, wn = wid >> 2;
    const int m0 = blockIdx.y * 128, n0 = blockIdx.x * 64;

    float acc[2][4][4];
#pragma unroll
    for (int s = 0; s < 2; s++)
#pragma unroll
        for (int n = 0; n < 4; n++)
#pragma unroll
            for (int i = 0; i < 4; i++) acc[s][n][i] = 0.0f;

    auto issue = [&](int c) {
        int st = c & 1, k0 = c * 32;
#pragma unroll
        for (int i = 0; i < 2; i++) {
            int e = tid + i * 256;                // 0..511: A 128 rows x 4 groups
            int r = e >> 2, sg = e & 3;
            cpa16(sA + st * GAP + r * 40 + sg * 8,
                  g_Ah + (size_t)(m0 + r) * DD + k0 + sg * 8);
        }
        {
            int r = tid >> 2, sg = tid & 3;       // B 64 rows x 4 groups
            cpa16(sB + st * GBP + r * 40 + sg * 8,
                  W + (size_t)(n0 + r) * DD + k0 + sg * 8);
        }
        cpa_commit();
    };

    issue(0);
    for (int c = 0; c < 32; c++) {
        if (c < 31) { issue(c + 1); cpa_wait1(); } else { cpa_wait0(); }
        __syncthreads();
        const __half* Ah = sA + (c & 1) * GAP;
        const __half* Bh = sB + (c & 1) * GBP;
#pragma unroll
        for (int kc = 0; kc < 32; kc += 16) {
            unsigned a[2][4];
#pragma unroll
            for (int s = 0; s < 2; s++) {
                int r0 = (wm * 32 + s * 16 + g) * 40, r1 = r0 + 8 * 40;
                a[s][0] = *(const unsigned*)&Ah[r0 + kc + 2 * t4];
                a[s][1] = *(const unsigned*)&Ah[r1 + kc + 2 * t4];
                a[s][2] = *(const unsigned*)&Ah[r0 + kc + 2 * t4 + 8];
                a[s][3] = *(const unsigned*)&Ah[r1 + kc + 2 * t4 + 8];
            }
#pragma unroll
            for (int n = 0; n < 4; n++) {
                int nb = (wn * 32 + n * 8 + g) * 40;
                unsigned b[2];
                b[0] = *(const unsigned*)&Bh[nb + kc + 2 * t4];
                b[1] = *(const unsigned*)&Bh[nb + kc + 2 * t4 + 8];
                mma_f16(acc[0][n], a[0], b);
                mma_f16(acc[1][n], a[1], b);
            }
        }
        __syncthreads();
    }

#pragma unroll
    for (int s = 0; s < 2; s++) {
#pragma unroll
        for (int n = 0; n < 4; n++) {
            int row = m0 + wm * 32 + s * 16 + g;
            int col = n0 + wn * 32 + n * 8 + 2 * t4;
            float b0 = bia[col] + bib[col];
            float b1 = bia[col + 1] + bib[col + 1];
            g_Gx[(size_t)row * NGATE + col]           = acc[s][n][0] + b0;
            g_Gx[(size_t)row * NGATE + col + 1]       = acc[s][n][1] + b1;
            g_Gx[(size_t)(row + 8) * NGATE + col]     = acc[s][n][2] + b0;
            g_Gx[(size_t)(row + 8) * NGATE + col + 1] = acc[s][n][3] + b1;
        }
    }
}

// ---------------- Recurrence v7: fp16 x1 (R14 v5 skeleton) ----------------
// 128 CTAs x 256 thr. CTA: 8 units = 32 gate rows. W fp16 packed: one uint4
// per (k16-pair, row, t4) -> 1 LDS.128 feeds 2 mma. 4-stage bulk pipeline.
__global__ void __launch_bounds__(NTHR, 1) lstm_layer_v7(
    const float* __restrict__ Whh, int layer, float* __restrict__ dout, int baridx) {
    extern __shared__ unsigned char smem_raw[];
    unsigned* pW = (unsigned*)smem_raw;
    float* Gred = (float*)(smem_raw + SM_GRED_OFF);           // [2][64][GP]
    const unsigned smem_base = (unsigned)__cvta_generic_to_shared(smem_raw);
    const unsigned stages_sm = smem_base + SM_STAGES_OFF;
    const unsigned mbar_sm   = smem_base + SM_MBAR_OFF;

    const int tid = threadIdx.x;
    const int wid = tid >> 5, lane = tid & 31;
    const int g = lane >> 2, t4 = lane & 3;
    const int mt = wid & 3;                 // batch m16 tile
    const int kh = wid >> 2;                // K half within 128-k chunk
    const int j0 = blockIdx.x * 8;

    if (tid == 0) {
#pragma unroll
        for (int s = 0; s < NSTAGE; s++) mbar_init(mbar_sm + s * 8, 1);
        fpa();
    }

    // W slice fp16 -> packed layout: pW[((kbp*32+row)*4+t4p)*4 + hp*2 + slot]
    // (kbp = k16-pair, hp = k16 parity in pair, slot = (k>>3)&1)
#pragma unroll 4
    for (int i = 0; i < 32; i++) {
        int e = tid + i * NTHR;              // 8192 float4
        int r = e >> 8, kf = e & 255;
        int q = r >> 3, jl = r & 7;
        int k0 = kf * 4;
        float4 v = *reinterpret_cast<const float4*>(
            &Whh[(size_t)(q * HH + j0 + jl) * HH + k0]);
        unsigned p01 = pack2h(v.x, v.y), p23 = pack2h(v.z, v.w);
        int kb = k0 >> 4, kbp = kb >> 1, hp = kb & 1;
        int t4p = (k0 >> 1) & 3, slot = (k0 >> 3) & 1;
        pW[(((kbp * 32 + r) * 4 + t4p) * 4) + hp * 2 + slot]     = p01;
        pW[(((kbp * 32 + r) * 4 + t4p + 1) * 4) + hp * 2 + slot] = p23;
    }
    __syncthreads();

    // c in registers: (b = tid&63, 2 units)
    const int cb = tid & 63;
    const int ug = tid >> 6;
    const int jl2 = 2 * ug;
    float creg[2];
#pragma unroll
    for (int i = 0; i < 2; i++)
        creg[i] = g_c[layer][cb * HH + j0 + jl2 + i];

    const int lm_row = (lane & 7) + ((lane >> 4) << 3);
    const int lm_col = mt * 16 + ((lane >> 3) & 1) * 8;
    const unsigned lm_byte = (unsigned)(lm_row * HTP + lm_col) * 2u;

    unsigned bar_target = 0;

    for (int t = 0; t < TT; t++) {
        const int par = t & 1, parn = par ^ 1;
        const __half* __restrict__ hTh = g_hT[par];

        if (tid == 0) {
            fpa();
#pragma unroll
            for (int c = 0; c < 3; c++) {
                unsigned mb = mbar_sm + c * 8;
                mbar_tx(mb, CHUNK_BYTES);
                bulk_g2s(stages_sm + c * CHUNK_BYTES,
                         hTh + (size_t)c * 128 * HTP, CHUNK_BYTES, mb);
            }
        }

        float2 pgx[4];
        {
            size_t gbase = ((size_t)t * BB + cb) * NGATE + j0 + jl2;
#pragma unroll
            for (int q = 0; q < 4; q++)
                pgx[q] = __ldg(reinterpret_cast<const float2*>(&g_Gx[gbase + q * HH]));
        }

        float acc[4][4];
#pragma unroll
        for (int n = 0; n < 4; n++)
#pragma unroll
            for (int i = 0; i < 4; i++) acc[n][i] = 0.0f;

#pragma unroll
        for (int c = 0; c < 8; c++) {
            const int s = c & (NSTAGE - 1);
            const unsigned parity = (c >= NSTAGE) ? 1u : 0u;
            mbar_wait(mbar_sm + s * 8, parity);
            const unsigned hb_addr = stages_sm + s * CHUNK_BYTES + lm_byte;
#pragma unroll
            for (int kp = 0; kp < 2; kp++) {
                int kl = kh * 64 + kp * 32;
                unsigned a0[4], a1[4];
                ldsm_x4t(a0, hb_addr + (unsigned)kl * (HTP * 2));
                ldsm_x4t(a1, hb_addr + (unsigned)(kl + 16) * (HTP * 2));
                int kbp = c * 4 + kh * 2 + kp;
#pragma unroll
                for (int n = 0; n < 4; n++) {
                    const uint4 w = *reinterpret_cast<const uint4*>(
                        &pW[((kbp * 32 + n * 8 + g) * 4 + t4) * 4]);
                    unsigned b0[2] = {w.x, w.y}, b1[2] = {w.z, w.w};
                    mma_f16(acc[n], a0, b0);
                    mma_f16(acc[n], a1, b1);
                }
            }
            __syncthreads();
            if (c < 5 && tid == 0) {
                int cn = c + 3;
                int sn = cn & (NSTAGE - 1);
                unsigned mb = mbar_sm + sn * 8;
                mbar_tx(mb, CHUNK_BYTES);
                bulk_g2s(stages_sm + sn * CHUNK_BYTES,
                         hTh + (size_t)cn * 128 * HTP, CHUNK_BYTES, mb);
            }
        }

        // split-K reduce via SMEM
#pragma unroll
        for (int n = 0; n < 4; n++) {
            int row = mt * 16 + g;
            int col = n * 8 + 2 * t4;
            float* gp = &Gred[(kh * 64 + row) * GP + col];
            gp[0] = acc[n][0];
            gp[1] = acc[n][1];
            gp[8 * GP] = acc[n][2];
            gp[8 * GP + 1] = acc[n][3];
        }
        __syncthreads();

        // gate/cell update
        {
            float2 gr0[4], gr1[4];
#pragma unroll
            for (int q = 0; q < 4; q++) {
                gr0[q] = *reinterpret_cast<const float2*>(&Gred[(cb) * GP + q * 8 + jl2]);
                gr1[q] = *reinterpret_cast<const float2*>(&Gred[(64 + cb) * GP + q * 8 + jl2]);
            }
#pragma unroll
            for (int i = 0; i < 2; i++) {
                float gi, gf, gg, go;
                if (i == 0) {
                    gi = pgx[0].x + gr0[0].x + gr1[0].x;
                    gf = pgx[1].x + gr0[1].x + gr1[1].x;
                    gg = pgx[2].x + gr0[2].x + gr1[2].x;
                    go = pgx[3].x + gr0[3].x + gr1[3].x;
                } else {
                    gi = pgx[0].y + gr0[0].y + gr1[0].y;
                    gf = pgx[1].y + gr0[1].y + gr1[1].y;
                    gg = pgx[2].y + gr0[2].y + gr1[2].y;
                    go = pgx[3].y + gr0[3].y + gr1[3].y;
                }
                float iv = sigmoidf_(gi);
                float fv = sigmoidf_(gf);
                float gv = tanhf(gg);
                float ov = sigmoidf_(go);
                float cn = fv * creg[i] + iv * gv;
                float hn = ov * tanhf(cn);
                creg[i] = cn;
                int j = j0 + jl2 + i;
                __half hb = __float2half_rn(hn);
                g_hT[parn][j * HTP + cb] = hb;
                if (t == TT - 1) {
                    g_h[layer][0][cb * HH + j] = hn;
                    g_c[layer][cb * HH + j] = cn;
                }
                if (dout) {
                    dout[(size_t)(cb * TT + t) * HH + j] = hn;        // [B,T,H]
                } else {
                    g_Ah[((size_t)t * BB + cb) * DD + j] = hb;        // y0 plane
                }
            }
        }

        // grid barrier
        bar_target += NCTA;
        __syncthreads();
        if (tid == 0) {
            __threadfence();
            atomicAdd(&g_bar[baridx], 1u);
            while (*((volatile unsigned*)&g_bar[baridx]) < bar_target) __nanosleep(32);
            __threadfence();
        }
        __syncthreads();
    }
}

__global__ void tail_kernel(float* __restrict__ out) {
    int i = blockIdx.x * blockDim.x + threadIdx.x;
    if (i >= BB * HH) return;
    out[(size_t)MM * HH + i]           = g_h[1][0][i];
    out[(size_t)MM * HH + BB * HH + i] = g_c[1][i];
}

extern "C" void kernel_launch(void* const* d_in, const int* in_sizes, int n_in,
                              void* d_out, int out_size) {
    int idx_in = 0, idxW0 = 3, idxW1 = 4, idxB0 = 5, idxB1 = 6, idxS0 = 1, idxS1 = 2;
    {
        int fin = -1, fW[2] = {-1, -1}, fB[2] = {-1, -1}, fS[2] = {-1, -1};
        int nW = 0, nB = 0, nS = 0;
        for (int i = 0; i < n_in; i++) {
            long s = in_sizes[i];
            if (s == (long)MM * DD)              fin = i;
            else if (s == (long)2 * NGATE * DD)  { if (nW < 2) fW[nW++] = i; }
            else if (s == (long)BB * 2 * HH)     { if (nS < 2) fS[nS++] = i; }
            else if (s == (long)2 * NGATE)       { if (nB < 2) fB[nB++] = i; }
        }
        if (fin >= 0 && nW == 2 && nB == 2 && nS == 2) {
            bool sig = fin < fW[0];
            idx_in = fin;
            idxW0 = sig ? fW[0] : fW[1];  idxW1 = sig ? fW[1] : fW[0];
            idxS0 = sig ? fS[0] : fS[1];  idxS1 = sig ? fS[1] : fS[0];
            idxB0 = fB[0];  idxB1 = fB[1];
        }
    }
    const float* input_ = (const float*)d_in[idx_in];
    const float* hx     = (const float*)d_in[idxS0];
    const float* cx     = (const float*)d_in[idxS1];
    const float* W_ih   = (const float*)d_in[idxW0];
    const float* W_hh   = (const float*)d_in[idxW1];
    const float* b_ih   = (const float*)d_in[idxB0];
    const float* b_hh   = (const float*)d_in[idxB1];
    float* out = (float*)d_out;

    cudaFuncSetAttribute(gemm_bias_v3,
                         cudaFuncAttributeMaxDynamicSharedMemorySize, GEMM_SMEM_BYTES);
    cudaFuncSetAttribute(lstm_layer_v7,
                         cudaFuncAttributeMaxDynamicSharedMemorySize, LSTM_SMEM_BYTES);

    init_kernel<<<512, 256>>>(hx, cx);
    prep_x_kernel<<<32768, 256>>>(input_);
    prep_w_kernel<<<8192, 256>>>(W_ih);

    gemm_bias_v3<<<dim3(64, 256), 256, GEMM_SMEM_BYTES>>>(0, b_ih, b_hh);
    hplane_init_kernel<<<256, 256>>>(0);
    lstm_layer_v7<<<NCTA, NTHR, LSTM_SMEM_BYTES>>>(W_hh, 0, nullptr, 0);

    gemm_bias_v3<<<dim3(64, 256), 256, GEMM_SMEM_BYTES>>>(1, b_ih + NGATE, b_hh + NGATE);
    hplane_init_kernel<<<256, 256>>>(1);
    lstm_layer_v7<<<NCTA, NTHR, LSTM_SMEM_BYTES>>>(W_hh + (size_t)NGATE * HH, 1, out, 1);

    if (out_size >= (int)((size_t)MM * HH + 2 * (size_t)BB * HH))
        tail_kernel<<<256, 256>>>(out);
}